// round 12
// baseline (speedup 1.0000x reference)
#include <cuda_runtime.h>
#include <cuda_fp16.h>
#include <math.h>
#include <stdint.h>

#define NN 50000
#define EE 800000
#define DD 128
#define HH 128
#define KU (DD + HH)
#define BN_EPS 1e-3f

#define SCAN_B 256
#define SCAN_NB ((NN + SCAN_B - 1) / SCAN_B)   // 196

// ---------------- scratch (device globals; no allocation allowed) ----------
__device__ __half g_Th[NN * HH];     // FFN intermediate (fp16)
__device__ __half g_Ph[NN * HH];     // prep output per node (fp16)
__device__ __half g_AGGh[NN * HH];   // aggregated messages (fp16)
__device__ float  g_PART[NN * HH];   // upd0 partial (fp32, epilogue add)
// weights: fp16, n-major  Wh[n][k]
__device__ __half g_Wp0h[HH * DD];
__device__ __half g_Wp1h[HH * HH];
__device__ __half g_Wu0h[HH * KU];   // row stride KU=256
__device__ __half g_Wu1h[HH * HH];
__device__ float  g_bp0[HH], g_bp1[HH], g_bu0[HH], g_bu1[HH];
// CSR combined: [cnt NN][cur NN][base 1][start NN]
__device__ int    g_csr[3 * NN + 1];
__device__ int    g_nbr[EE];
__device__ float  g_wgt[EE];

#define CSR_CNT   (g_csr)
#define CSR_CUR   (g_csr + NN)
#define CSR_BASE  (g_csr + 2 * NN)
#define CSR_START (g_csr + 2 * NN + 1)

// ---------------- streams/events (lazy init on first, non-captured call) ----
struct StreamPack {
    cudaStream_t s1, s2;
    cudaEvent_t ev_root, ev_fold, ev_csr, ev_u0a;
    StreamPack() {
        cudaStreamCreateWithFlags(&s1, cudaStreamNonBlocking);
        cudaStreamCreateWithFlags(&s2, cudaStreamNonBlocking);
        cudaEventCreateWithFlags(&ev_root, cudaEventDisableTiming);
        cudaEventCreateWithFlags(&ev_fold, cudaEventDisableTiming);
        cudaEventCreateWithFlags(&ev_csr,  cudaEventDisableTiming);
        cudaEventCreateWithFlags(&ev_u0a,  cudaEventDisableTiming);
    }
};

// ---------------- BN fold (4 matrices, one launch) --------------------------
struct FoldArgs {
    const float *g, *b, *m, *v, *W, *bi;
    __half *Wo;
    float *bo;
    int K, ldw;
};

__global__ void fold4_kernel(FoldArgs a0, FoldArgs a1, FoldArgs a2, FoldArgs a3) {
    FoldArgs a;
    switch (blockIdx.y) {
        case 0: a = a0; break;
        case 1: a = a1; break;
        case 2: a = a2; break;
        default: a = a3; break;
    }
    int j = blockIdx.x;        // output column (n)
    int k = threadIdx.x;       // input row (k)
    __shared__ float red[256];
    float contrib = 0.0f;
    if (k < a.K) {
        float s = a.g[k] * rsqrtf(a.v[k] + BN_EPS);
        float t = a.b[k] - a.m[k] * s;
        float w = a.W[k * HH + j];
        a.Wo[j * a.ldw + k] = __float2half(s * w);   // transposed, fp16
        contrib = t * w;
    }
    red[k] = contrib;
    __syncthreads();
    for (int st = 128; st > 0; st >>= 1) {
        if (k < st) red[k] += red[k + st];
        __syncthreads();
    }
    if (k == 0) a.bo[j] = a.bi[j] + red[0];
}

// ---------------- CSR build --------------------------------------------------
__global__ void count_kernel(const int* __restrict__ edges) {
    int e = blockIdx.x * blockDim.x + threadIdx.x;
    if (e < EE) atomicAdd(&CSR_CNT[edges[e]], 1);
}

__global__ void scan_fused_kernel() {
    __shared__ int sh[SCAN_B];
    __shared__ int base_sh;
    int t = threadIdx.x;
    int i = blockIdx.x * SCAN_B + t;
    int v = (i < NN) ? CSR_CNT[i] : 0;
    sh[t] = v;
    __syncthreads();
    for (int ofs = 1; ofs < SCAN_B; ofs <<= 1) {
        int u = (t >= ofs) ? sh[t - ofs] : 0;
        __syncthreads();
        sh[t] += u;
        __syncthreads();
    }
    if (t == SCAN_B - 1) base_sh = atomicAdd(CSR_BASE, sh[t]);
    __syncthreads();
    if (i < NN) CSR_START[i] = base_sh + sh[t] - v;
}

__global__ void fill_kernel(const int* __restrict__ edges, const float* __restrict__ ew) {
    int e = blockIdx.x * blockDim.x + threadIdx.x;
    if (e < EE) {
        int dst = edges[e];
        int nbr = edges[EE + e];
        int pos = CSR_START[dst] + atomicAdd(&CSR_CUR[dst], 1);
        g_nbr[pos] = nbr;
        g_wgt[pos] = ew[e];
    }
}

// ---------------- aggregation: one warp per node, fp16 in / fp16 out --------
__global__ void aggregate_kernel() {
    int node = (blockIdx.x * blockDim.x + threadIdx.x) >> 5;
    int lane = threadIdx.x & 31;
    if (node >= NN) return;
    int s = CSR_START[node];
    int cnt = CSR_CNT[node];
    int e = s + cnt;
    float4 acc = make_float4(0.f, 0.f, 0.f, 0.f);
    int i = s;
    for (; i + 4 <= e; i += 4) {
        int   nb0 = __ldg(&g_nbr[i]),     nb1 = __ldg(&g_nbr[i + 1]);
        int   nb2 = __ldg(&g_nbr[i + 2]), nb3 = __ldg(&g_nbr[i + 3]);
        float w0 = __ldg(&g_wgt[i]),      w1 = __ldg(&g_wgt[i + 1]);
        float w2 = __ldg(&g_wgt[i + 2]),  w3 = __ldg(&g_wgt[i + 3]);
        const __half2* p0 = (const __half2*)&g_Ph[nb0 * HH + lane * 4];
        const __half2* p1 = (const __half2*)&g_Ph[nb1 * HH + lane * 4];
        const __half2* p2 = (const __half2*)&g_Ph[nb2 * HH + lane * 4];
        const __half2* p3 = (const __half2*)&g_Ph[nb3 * HH + lane * 4];
        float2 a0 = __half22float2(p0[0]), b0 = __half22float2(p0[1]);
        float2 a1 = __half22float2(p1[0]), b1 = __half22float2(p1[1]);
        float2 a2 = __half22float2(p2[0]), b2 = __half22float2(p2[1]);
        float2 a3 = __half22float2(p3[0]), b3 = __half22float2(p3[1]);
        acc.x += w0 * a0.x + w1 * a1.x + w2 * a2.x + w3 * a3.x;
        acc.y += w0 * a0.y + w1 * a1.y + w2 * a2.y + w3 * a3.y;
        acc.z += w0 * b0.x + w1 * b1.x + w2 * b2.x + w3 * b3.x;
        acc.w += w0 * b0.y + w1 * b1.y + w2 * b2.y + w3 * b3.y;
    }
    for (; i < e; i++) {
        int nb  = __ldg(&g_nbr[i]);
        float w = __ldg(&g_wgt[i]);
        const __half2* p = (const __half2*)&g_Ph[nb * HH + lane * 4];
        float2 a = __half22float2(p[0]), b = __half22float2(p[1]);
        acc.x += w * a.x; acc.y += w * a.y; acc.z += w * b.x; acc.w += w * b.y;
    }
    float inv = (cnt > 0) ? 1.0f / (float)cnt : 0.0f;
    __half2 h0 = __floats2half2_rn(acc.x * inv, acc.y * inv);
    __half2 h1 = __floats2half2_rn(acc.z * inv, acc.w * inv);
    uint2 o;
    o.x = *(uint32_t*)&h0;
    o.y = *(uint32_t*)&h1;
    *(uint2*)&g_AGGh[node * HH + lane * 4] = o;
}

// ---------------- fp16 one-shot-smem GEMM, K=128 fixed ----------------------
// Whole A-tile (128x128) and whole B (128x128) staged in smem: ONE barrier.
// MODE 0: fp32 out, gelu(acc+bias)
// MODE 1: fp32 out, raw acc
// MODE 3: fp16 out, gelu(acc+bias)
// MODE 4: fp16 out, gelu(acc+bias+Cadd)
__device__ __forceinline__ float gelu_exact(float x) {
    return 0.5f * x * (1.0f + erff(x * 0.70710678118654752f));
}

__device__ __forceinline__ void mma_f16(float* d, const uint32_t* a, const uint32_t* b) {
    asm volatile(
        "mma.sync.aligned.m16n8k16.row.col.f32.f16.f16.f32 "
        "{%0,%1,%2,%3}, {%4,%5,%6,%7}, {%8,%9}, {%0,%1,%2,%3};\n"
        : "+f"(d[0]), "+f"(d[1]), "+f"(d[2]), "+f"(d[3])
        : "r"(a[0]), "r"(a[1]), "r"(a[2]), "r"(a[3]), "r"(b[0]), "r"(b[1]));
}

#define BM 128
#define KK 128
#define HS 136   // smem row stride in halves (128 + 8): frag banks 4*gi+ti, distinct
#define GEMM_SMEM (2 * BM * HS * (int)sizeof(__half))   // 69632 B

template <int MODE, bool AHALF>
__global__ __launch_bounds__(256, 2) void gemm_f16_os(
    const void* __restrict__ Av,
    const __half* __restrict__ Wh, int ldb,
    const float* __restrict__ bias,
    const float* __restrict__ Cadd,
    void* __restrict__ Cv, int M)
{
    extern __shared__ __half sm[];
    __half* Asp = sm;                 // [128][HS]
    __half* Bsp = sm + BM * HS;       // [128][HS]

    const int tid  = threadIdx.x;
    const int lane = tid & 31;
    const int wid  = tid >> 5;
    const int wm = (wid & 3) * 32;
    const int wn = (wid >> 2) * 64;
    const int bm = blockIdx.x * BM;

    const int lr    = tid >> 1;        // 0..127
    const int hbase = (tid & 1) * 64;  // half-offset within row
    const int grow  = bm + lr;
    const bool rok  = (grow < M);

    const int gi = lane >> 2;
    const int ti = lane & 3;

    // ---- load everything, one barrier ----
#pragma unroll
    for (int j = 0; j < 8; j++) {
        *(uint4*)&Bsp[lr * HS + hbase + 8 * j] =
            *(const uint4*)&Wh[lr * ldb + hbase + 8 * j];
    }
    if (AHALF) {
        const __half* Ah = (const __half*)Av;
#pragma unroll
        for (int j = 0; j < 8; j++) {
            uint4 v = make_uint4(0, 0, 0, 0);
            if (rok) v = *(const uint4*)&Ah[grow * KK + hbase + 8 * j];
            *(uint4*)&Asp[lr * HS + hbase + 8 * j] = v;
        }
    } else {
        const float* Af = (const float*)Av;
#pragma unroll
        for (int j = 0; j < 8; j++) {
            float4 x = make_float4(0.f, 0.f, 0.f, 0.f), y = x;
            if (rok) {
                x = *(const float4*)&Af[grow * KK + hbase + 8 * j];
                y = *(const float4*)&Af[grow * KK + hbase + 8 * j + 4];
            }
            __half2 h0 = __floats2half2_rn(x.x, x.y);
            __half2 h1 = __floats2half2_rn(x.z, x.w);
            __half2 h2 = __floats2half2_rn(y.x, y.y);
            __half2 h3 = __floats2half2_rn(y.z, y.w);
            uint4 v;
            v.x = *(uint32_t*)&h0; v.y = *(uint32_t*)&h1;
            v.z = *(uint32_t*)&h2; v.w = *(uint32_t*)&h3;
            *(uint4*)&Asp[lr * HS + hbase + 8 * j] = v;
        }
    }
    __syncthreads();

    // ---- 128 MMAs per warp, no further barriers ----
    float acc[2][8][4];
#pragma unroll
    for (int i = 0; i < 2; i++)
#pragma unroll
        for (int j = 0; j < 8; j++)
#pragma unroll
            for (int c = 0; c < 4; c++) acc[i][j][c] = 0.0f;

#pragma unroll
    for (int kb = 0; kb < 8; kb++) {
        const int k0 = kb * 16;
        uint32_t af[2][4];
#pragma unroll
        for (int i = 0; i < 2; i++) {
            const int r = wm + 16 * i + gi;
            af[i][0] = *(const uint32_t*)&Asp[r * HS + k0 + 2 * ti];
            af[i][1] = *(const uint32_t*)&Asp[(r + 8) * HS + k0 + 2 * ti];
            af[i][2] = *(const uint32_t*)&Asp[r * HS + k0 + 2 * ti + 8];
            af[i][3] = *(const uint32_t*)&Asp[(r + 8) * HS + k0 + 2 * ti + 8];
        }
        uint32_t bf[8][2];
#pragma unroll
        for (int j = 0; j < 8; j++) {
            const int n = wn + 8 * j + gi;
            bf[j][0] = *(const uint32_t*)&Bsp[n * HS + k0 + 2 * ti];
            bf[j][1] = *(const uint32_t*)&Bsp[n * HS + k0 + 2 * ti + 8];
        }
#pragma unroll
        for (int i = 0; i < 2; i++)
#pragma unroll
            for (int j = 0; j < 8; j++)
                mma_f16(acc[i][j], af[i], bf[j]);
    }

    // ---- epilogue ----
    float* C = (float*)Cv;
    __half* Ch = (__half*)Cv;
#pragma unroll
    for (int j = 0; j < 8; j++) {
        const int col = wn + 8 * j + ti * 2;
        float b0 = 0.f, b1 = 0.f;
        if (MODE != 1) { b0 = bias[col]; b1 = bias[col + 1]; }
#pragma unroll
        for (int i = 0; i < 2; i++) {
            const int r0 = bm + wm + 16 * i + gi;
            const int r1 = r0 + 8;
            if (r0 < M) {
                if (MODE == 1) {
                    *(float2*)&C[r0 * 128 + col] = make_float2(acc[i][j][0], acc[i][j][1]);
                } else if (MODE == 3) {
                    *(__half2*)&Ch[r0 * 128 + col] = __floats2half2_rn(
                        gelu_exact(acc[i][j][0] + b0), gelu_exact(acc[i][j][1] + b1));
                } else if (MODE == 4) {
                    *(__half2*)&Ch[r0 * 128 + col] = __floats2half2_rn(
                        gelu_exact(acc[i][j][0] + b0 + Cadd[r0 * 128 + col]),
                        gelu_exact(acc[i][j][1] + b1 + Cadd[r0 * 128 + col + 1]));
                } else {
                    float2 o;
                    o.x = gelu_exact(acc[i][j][0] + b0);
                    o.y = gelu_exact(acc[i][j][1] + b1);
                    *(float2*)&C[r0 * 128 + col] = o;
                }
            }
            if (r1 < M) {
                if (MODE == 1) {
                    *(float2*)&C[r1 * 128 + col] = make_float2(acc[i][j][2], acc[i][j][3]);
                } else if (MODE == 3) {
                    *(__half2*)&Ch[r1 * 128 + col] = __floats2half2_rn(
                        gelu_exact(acc[i][j][2] + b0), gelu_exact(acc[i][j][3] + b1));
                } else if (MODE == 4) {
                    *(__half2*)&Ch[r1 * 128 + col] = __floats2half2_rn(
                        gelu_exact(acc[i][j][2] + b0 + Cadd[r1 * 128 + col]),
                        gelu_exact(acc[i][j][3] + b1 + Cadd[r1 * 128 + col + 1]));
                } else {
                    float2 o;
                    o.x = gelu_exact(acc[i][j][2] + b0);
                    o.y = gelu_exact(acc[i][j][3] + b1);
                    *(float2*)&C[r1 * 128 + col] = o;
                }
            }
        }
    }
}

// ---------------- launch -----------------------------------------------------
extern "C" void kernel_launch(void* const* d_in, const int* in_sizes, int n_in,
                              void* d_out, int out_size) {
    static StreamPack sp;   // first call = correctness run (not captured)

    const float* node_repr = (const float*)d_in[0];
    const int*   edges     = (const int*)d_in[1];
    const float* ew        = (const float*)d_in[2];
    const float *p0g = (const float*)d_in[3],  *p0b = (const float*)d_in[4],
                *p0m = (const float*)d_in[5],  *p0v = (const float*)d_in[6],
                *p0W = (const float*)d_in[7],  *p0bi = (const float*)d_in[8];
    const float *p1g = (const float*)d_in[9],  *p1b = (const float*)d_in[10],
                *p1m = (const float*)d_in[11], *p1v = (const float*)d_in[12],
                *p1W = (const float*)d_in[13], *p1bi = (const float*)d_in[14];
    const float *u0g = (const float*)d_in[15], *u0b = (const float*)d_in[16],
                *u0m = (const float*)d_in[17], *u0v = (const float*)d_in[18],
                *u0W = (const float*)d_in[19], *u0bi = (const float*)d_in[20];
    const float *u1g = (const float*)d_in[21], *u1b = (const float*)d_in[22],
                *u1m = (const float*)d_in[23], *u1v = (const float*)d_in[24],
                *u1W = (const float*)d_in[25], *u1bi = (const float*)d_in[26];
    float* out = (float*)d_out;

    __half *Wp0h, *Wp1h, *Wu0h, *Wu1h, *Ph, *Th, *AGGh;
    float *bp0, *bp1, *bu0, *bu1, *PART;
    int* csr;
    cudaGetSymbolAddress((void**)&Wp0h, g_Wp0h);
    cudaGetSymbolAddress((void**)&Wp1h, g_Wp1h);
    cudaGetSymbolAddress((void**)&Wu0h, g_Wu0h);
    cudaGetSymbolAddress((void**)&Wu1h, g_Wu1h);
    cudaGetSymbolAddress((void**)&bp0, g_bp0);
    cudaGetSymbolAddress((void**)&bp1, g_bp1);
    cudaGetSymbolAddress((void**)&bu0, g_bu0);
    cudaGetSymbolAddress((void**)&bu1, g_bu1);
    cudaGetSymbolAddress((void**)&Th,   g_Th);
    cudaGetSymbolAddress((void**)&Ph,   g_Ph);
    cudaGetSymbolAddress((void**)&AGGh, g_AGGh);
    cudaGetSymbolAddress((void**)&PART, g_PART);
    cudaGetSymbolAddress((void**)&csr,  g_csr);

    // opt-in dynamic smem > 48KB (idempotent; fine on every call)
    cudaFuncSetAttribute(gemm_f16_os<1, false>, cudaFuncAttributeMaxDynamicSharedMemorySize, GEMM_SMEM);
    cudaFuncSetAttribute(gemm_f16_os<3, false>, cudaFuncAttributeMaxDynamicSharedMemorySize, GEMM_SMEM);
    cudaFuncSetAttribute(gemm_f16_os<3, true >, cudaFuncAttributeMaxDynamicSharedMemorySize, GEMM_SMEM);
    cudaFuncSetAttribute(gemm_f16_os<4, true >, cudaFuncAttributeMaxDynamicSharedMemorySize, GEMM_SMEM);
    cudaFuncSetAttribute(gemm_f16_os<0, true >, cudaFuncAttributeMaxDynamicSharedMemorySize, GEMM_SMEM);

    cudaStream_t s0 = 0, s1 = sp.s1, s2 = sp.s2;
    const int gm = (NN + BM - 1) / BM;

    // fork point
    cudaEventRecord(sp.ev_root, s0);
    cudaStreamWaitEvent(s1, sp.ev_root, 0);

    // --- s1: CSR chain ---
    cudaMemsetAsync(csr, 0, (2 * NN + 1) * sizeof(int), s1);
    count_kernel<<<(EE + 255) / 256, 256, 0, s1>>>(edges);
    scan_fused_kernel<<<SCAN_NB, SCAN_B, 0, s1>>>();
    fill_kernel<<<(EE + 255) / 256, 256, 0, s1>>>(edges, ew);
    cudaEventRecord(sp.ev_csr, s1);

    // --- s0: fold (fp16 transposed weights) ---
    FoldArgs fa0 = {p0g, p0b, p0m, p0v, p0W, p0bi, Wp0h, bp0, DD, DD};
    FoldArgs fa1 = {p1g, p1b, p1m, p1v, p1W, p1bi, Wp1h, bp1, HH, HH};
    FoldArgs fa2 = {u0g, u0b, u0m, u0v, u0W, u0bi, Wu0h, bu0, KU, KU};
    FoldArgs fa3 = {u1g, u1b, u1m, u1v, u1W, u1bi, Wu1h, bu1, HH, HH};
    fold4_kernel<<<dim3(128, 4), 256, 0, s0>>>(fa0, fa1, fa2, fa3);
    cudaEventRecord(sp.ev_fold, s0);

    // --- s2: upd0 partial = node_repr @ Wu0[:, 0:128] -> PART (fp32) ---
    cudaStreamWaitEvent(s2, sp.ev_fold, 0);
    gemm_f16_os<1, false><<<gm, 256, GEMM_SMEM, s2>>>(node_repr, Wu0h, KU, nullptr, nullptr, PART, NN);
    cudaEventRecord(sp.ev_u0a, s2);

    // --- s0: prep FFN (all fp16 intermediates) ---
    gemm_f16_os<3, false><<<gm, 256, GEMM_SMEM, s0>>>(node_repr, Wp0h, DD, bp0, nullptr, Th, NN);
    gemm_f16_os<3, true ><<<gm, 256, GEMM_SMEM, s0>>>(Th,        Wp1h, HH, bp1, nullptr, Ph, NN);

    // join CSR, aggregate (fp16 in/out)
    cudaStreamWaitEvent(s0, sp.ev_csr, 0);
    aggregate_kernel<<<(NN * 32 + 255) / 256, 256, 0, s0>>>();

    // join upd0 partial; upd0b: gelu(AGG @ Wu0[:, 128:256] + PART + bias) -> Th
    cudaStreamWaitEvent(s0, sp.ev_u0a, 0);
    gemm_f16_os<4, true ><<<gm, 256, GEMM_SMEM, s0>>>(AGGh, Wu0h + 128, KU, bu0, PART, Th, NN);
    gemm_f16_os<0, true ><<<gm, 256, GEMM_SMEM, s0>>>(Th, Wu1h, HH, bu1, nullptr, out, NN);
}

// round 13
// speedup vs baseline: 1.1312x; 1.1312x over previous
#include <cuda_runtime.h>
#include <cuda_fp16.h>
#include <math.h>
#include <stdint.h>

#define NN 50000
#define EE 800000
#define DD 128
#define HH 128
#define KU (DD + HH)
#define BN_EPS 1e-3f

#define SCAN_B 256
#define SCAN_NB ((NN + SCAN_B - 1) / SCAN_B)   // 196

// ---------------- scratch (device globals; no allocation allowed) ----------
__device__ __half g_Th[NN * HH];     // FFN intermediate (fp16)
__device__ __half g_Ph[NN * HH];     // prep output per node (fp16)
__device__ __half g_AGGh[NN * HH];   // aggregated messages (fp16)
__device__ float  g_PART[NN * HH];   // upd0 partial (fp32, epilogue add)
// weights: fp16, n-major  Wh[n][k]
__device__ __half g_Wp0h[HH * DD];
__device__ __half g_Wp1h[HH * HH];
__device__ __half g_Wu0h[HH * KU];   // row stride KU=256
__device__ __half g_Wu1h[HH * HH];
__device__ float  g_bp0[HH], g_bp1[HH], g_bu0[HH], g_bu1[HH];
// CSR combined: [cnt NN][cur NN][base 1][start NN]
__device__ int    g_csr[3 * NN + 1];
__device__ int    g_nbr[EE];
__device__ float  g_wgt[EE];

#define CSR_CNT   (g_csr)
#define CSR_CUR   (g_csr + NN)
#define CSR_BASE  (g_csr + 2 * NN)
#define CSR_START (g_csr + 2 * NN + 1)

// ---------------- streams/events (lazy init on first, non-captured call) ----
struct StreamPack {
    cudaStream_t s1, s2;
    cudaEvent_t ev_root, ev_fold, ev_csr, ev_u0a;
    StreamPack() {
        cudaStreamCreateWithFlags(&s1, cudaStreamNonBlocking);
        cudaStreamCreateWithFlags(&s2, cudaStreamNonBlocking);
        cudaEventCreateWithFlags(&ev_root, cudaEventDisableTiming);
        cudaEventCreateWithFlags(&ev_fold, cudaEventDisableTiming);
        cudaEventCreateWithFlags(&ev_csr,  cudaEventDisableTiming);
        cudaEventCreateWithFlags(&ev_u0a,  cudaEventDisableTiming);
    }
};

// ---------------- BN fold (4 matrices, one launch) --------------------------
struct FoldArgs {
    const float *g, *b, *m, *v, *W, *bi;
    __half *Wo;
    float *bo;
    int K, ldw;
};

__global__ void fold4_kernel(FoldArgs a0, FoldArgs a1, FoldArgs a2, FoldArgs a3) {
    FoldArgs a;
    switch (blockIdx.y) {
        case 0: a = a0; break;
        case 1: a = a1; break;
        case 2: a = a2; break;
        default: a = a3; break;
    }
    int j = blockIdx.x;        // output column (n)
    int k = threadIdx.x;       // input row (k)
    __shared__ float red[256];
    float contrib = 0.0f;
    if (k < a.K) {
        float s = a.g[k] * rsqrtf(a.v[k] + BN_EPS);
        float t = a.b[k] - a.m[k] * s;
        float w = a.W[k * HH + j];
        a.Wo[j * a.ldw + k] = __float2half(s * w);   // transposed, fp16
        contrib = t * w;
    }
    red[k] = contrib;
    __syncthreads();
    for (int st = 128; st > 0; st >>= 1) {
        if (k < st) red[k] += red[k + st];
        __syncthreads();
    }
    if (k == 0) a.bo[j] = a.bi[j] + red[0];
}

// ---------------- CSR build --------------------------------------------------
__global__ void count_kernel(const int* __restrict__ edges) {
    int e = blockIdx.x * blockDim.x + threadIdx.x;
    if (e < EE) atomicAdd(&CSR_CNT[edges[e]], 1);
}

__global__ void scan_fused_kernel() {
    __shared__ int sh[SCAN_B];
    __shared__ int base_sh;
    int t = threadIdx.x;
    int i = blockIdx.x * SCAN_B + t;
    int v = (i < NN) ? CSR_CNT[i] : 0;
    sh[t] = v;
    __syncthreads();
    for (int ofs = 1; ofs < SCAN_B; ofs <<= 1) {
        int u = (t >= ofs) ? sh[t - ofs] : 0;
        __syncthreads();
        sh[t] += u;
        __syncthreads();
    }
    if (t == SCAN_B - 1) base_sh = atomicAdd(CSR_BASE, sh[t]);
    __syncthreads();
    if (i < NN) CSR_START[i] = base_sh + sh[t] - v;
}

__global__ void fill_kernel(const int* __restrict__ edges, const float* __restrict__ ew) {
    int e = blockIdx.x * blockDim.x + threadIdx.x;
    if (e < EE) {
        int dst = edges[e];
        int nbr = edges[EE + e];
        int pos = CSR_START[dst] + atomicAdd(&CSR_CUR[dst], 1);
        g_nbr[pos] = nbr;
        g_wgt[pos] = ew[e];
    }
}

// ---------------- aggregation: one warp per node, fp16 in / fp16 out --------
__global__ void aggregate_kernel() {
    int node = (blockIdx.x * blockDim.x + threadIdx.x) >> 5;
    int lane = threadIdx.x & 31;
    if (node >= NN) return;
    int s = CSR_START[node];
    int cnt = CSR_CNT[node];
    int e = s + cnt;
    float4 acc = make_float4(0.f, 0.f, 0.f, 0.f);
    int i = s;
    for (; i + 4 <= e; i += 4) {
        int   nb0 = __ldg(&g_nbr[i]),     nb1 = __ldg(&g_nbr[i + 1]);
        int   nb2 = __ldg(&g_nbr[i + 2]), nb3 = __ldg(&g_nbr[i + 3]);
        float w0 = __ldg(&g_wgt[i]),      w1 = __ldg(&g_wgt[i + 1]);
        float w2 = __ldg(&g_wgt[i + 2]),  w3 = __ldg(&g_wgt[i + 3]);
        const __half2* p0 = (const __half2*)&g_Ph[nb0 * HH + lane * 4];
        const __half2* p1 = (const __half2*)&g_Ph[nb1 * HH + lane * 4];
        const __half2* p2 = (const __half2*)&g_Ph[nb2 * HH + lane * 4];
        const __half2* p3 = (const __half2*)&g_Ph[nb3 * HH + lane * 4];
        float2 a0 = __half22float2(p0[0]), b0 = __half22float2(p0[1]);
        float2 a1 = __half22float2(p1[0]), b1 = __half22float2(p1[1]);
        float2 a2 = __half22float2(p2[0]), b2 = __half22float2(p2[1]);
        float2 a3 = __half22float2(p3[0]), b3 = __half22float2(p3[1]);
        acc.x += w0 * a0.x + w1 * a1.x + w2 * a2.x + w3 * a3.x;
        acc.y += w0 * a0.y + w1 * a1.y + w2 * a2.y + w3 * a3.y;
        acc.z += w0 * b0.x + w1 * b1.x + w2 * b2.x + w3 * b3.x;
        acc.w += w0 * b0.y + w1 * b1.y + w2 * b2.y + w3 * b3.y;
    }
    for (; i < e; i++) {
        int nb  = __ldg(&g_nbr[i]);
        float w = __ldg(&g_wgt[i]);
        const __half2* p = (const __half2*)&g_Ph[nb * HH + lane * 4];
        float2 a = __half22float2(p[0]), b = __half22float2(p[1]);
        acc.x += w * a.x; acc.y += w * a.y; acc.z += w * b.x; acc.w += w * b.y;
    }
    float inv = (cnt > 0) ? 1.0f / (float)cnt : 0.0f;
    __half2 h0 = __floats2half2_rn(acc.x * inv, acc.y * inv);
    __half2 h1 = __floats2half2_rn(acc.z * inv, acc.w * inv);
    uint2 o;
    o.x = *(uint32_t*)&h0;
    o.y = *(uint32_t*)&h1;
    *(uint2*)&g_AGGh[node * HH + lane * 4] = o;
}

// ---------------- fp16 pipelined GEMM, K=128, double-buffered smem ----------
// MODE 0: fp32 out, gelu(acc+bias)
// MODE 1: fp32 out, raw acc
// MODE 3: fp16 out, gelu(acc+bias)
// MODE 4: fp16 out, gelu(acc+bias+Cadd)
__device__ __forceinline__ float gelu_exact(float x) {
    return 0.5f * x * (1.0f + erff(x * 0.70710678118654752f));
}

__device__ __forceinline__ void mma_f16(float* d, const uint32_t* a, const uint32_t* b) {
    asm volatile(
        "mma.sync.aligned.m16n8k16.row.col.f32.f16.f16.f32 "
        "{%0,%1,%2,%3}, {%4,%5,%6,%7}, {%8,%9}, {%0,%1,%2,%3};\n"
        : "+f"(d[0]), "+f"(d[1]), "+f"(d[2]), "+f"(d[3])
        : "r"(a[0]), "r"(a[1]), "r"(a[2]), "r"(a[3]), "r"(b[0]), "r"(b[1]));
}

#define BM 128
#define BK 16
#define KK 128
#define HS 24      // smem row stride in halves (16 + 8 pad): conflict-free frags

template <int MODE, bool AHALF>
__global__ __launch_bounds__(256, 2) void gemm_f16_k128(
    const void* __restrict__ Av,
    const __half* __restrict__ Wh, int ldb,
    const float* __restrict__ bias,
    const float* __restrict__ Cadd,
    void* __restrict__ Cv, int M)
{
    __shared__ __half As[2][BM][HS];   // [stage][m][k]
    __shared__ __half Bs[2][BM][HS];   // [stage][n][k]

    const int tid  = threadIdx.x;
    const int lane = tid & 31;
    const int wid  = tid >> 5;
    const int wm = (wid & 3) * 32;
    const int wn = (wid >> 2) * 64;
    const int bm = blockIdx.x * BM;

    // loaders: row = tid>>1 (128 rows), k-segment = (tid&1)*8 (8 halves)
    const int lr  = tid >> 1;
    const int seg = (tid & 1) * 8;
    const int grow = bm + lr;
    const bool rok = (grow < M);

    const int gi = lane >> 2;
    const int ti = lane & 3;

    float acc[2][8][4];
#pragma unroll
    for (int i = 0; i < 2; i++)
#pragma unroll
        for (int j = 0; j < 8; j++)
#pragma unroll
            for (int c = 0; c < 4; c++) acc[i][j][c] = 0.0f;

    // tile loader into registers
    uint4 avr, bvr;
    auto load_tile = [&](int kc) {
        if (AHALF) {
            avr = make_uint4(0, 0, 0, 0);
            if (rok) avr = *(const uint4*)&((const __half*)Av)[grow * KK + kc + seg];
        } else {
            float4 x = make_float4(0.f,0.f,0.f,0.f), y = x;
            if (rok) {
                const float* ap = &((const float*)Av)[grow * KK + kc + seg];
                x = *(const float4*)(ap);
                y = *(const float4*)(ap + 4);
            }
            __half2 h0 = __floats2half2_rn(x.x, x.y);
            __half2 h1 = __floats2half2_rn(x.z, x.w);
            __half2 h2 = __floats2half2_rn(y.x, y.y);
            __half2 h3 = __floats2half2_rn(y.z, y.w);
            avr.x = *(uint32_t*)&h0; avr.y = *(uint32_t*)&h1;
            avr.z = *(uint32_t*)&h2; avr.w = *(uint32_t*)&h3;
        }
        bvr = *(const uint4*)&Wh[lr * ldb + kc + seg];
    };

    // preload tile 0 into stage 0
    load_tile(0);
    *(uint4*)&As[0][lr][seg] = avr;
    *(uint4*)&Bs[0][lr][seg] = bvr;
    __syncthreads();

#pragma unroll
    for (int kb = 0; kb < KK / BK; kb++) {
        const int buf = kb & 1;
        if (kb + 1 < KK / BK) load_tile((kb + 1) * BK);

        // compute on current stage (no barrier inside)
        uint32_t af[2][4];
#pragma unroll
        for (int i = 0; i < 2; i++) {
            const int r = wm + 16 * i + gi;
            af[i][0] = *(const uint32_t*)&As[buf][r][2 * ti];
            af[i][1] = *(const uint32_t*)&As[buf][r + 8][2 * ti];
            af[i][2] = *(const uint32_t*)&As[buf][r][2 * ti + 8];
            af[i][3] = *(const uint32_t*)&As[buf][r + 8][2 * ti + 8];
        }
        uint32_t bf[8][2];
#pragma unroll
        for (int j = 0; j < 8; j++) {
            const int n = wn + 8 * j + gi;
            bf[j][0] = *(const uint32_t*)&Bs[buf][n][2 * ti];
            bf[j][1] = *(const uint32_t*)&Bs[buf][n][2 * ti + 8];
        }
#pragma unroll
        for (int i = 0; i < 2; i++)
#pragma unroll
            for (int j = 0; j < 8; j++)
                mma_f16(acc[i][j], af[i], bf[j]);

        // store next tile into the idle stage; ONE barrier per iteration
        if (kb + 1 < KK / BK) {
            *(uint4*)&As[buf ^ 1][lr][seg] = avr;
            *(uint4*)&Bs[buf ^ 1][lr][seg] = bvr;
            __syncthreads();
        }
    }

    // ---- epilogue ----
    float* C = (float*)Cv;
    __half* Ch = (__half*)Cv;
#pragma unroll
    for (int j = 0; j < 8; j++) {
        const int col = wn + 8 * j + ti * 2;
        float b0 = 0.f, b1 = 0.f;
        if (MODE != 1) { b0 = bias[col]; b1 = bias[col + 1]; }
#pragma unroll
        for (int i = 0; i < 2; i++) {
            const int r0 = bm + wm + 16 * i + gi;
            const int r1 = r0 + 8;
            if (r0 < M) {
                if (MODE == 1) {
                    *(float2*)&C[r0 * 128 + col] = make_float2(acc[i][j][0], acc[i][j][1]);
                } else if (MODE == 3) {
                    *(__half2*)&Ch[r0 * 128 + col] = __floats2half2_rn(
                        gelu_exact(acc[i][j][0] + b0), gelu_exact(acc[i][j][1] + b1));
                } else if (MODE == 4) {
                    *(__half2*)&Ch[r0 * 128 + col] = __floats2half2_rn(
                        gelu_exact(acc[i][j][0] + b0 + Cadd[r0 * 128 + col]),
                        gelu_exact(acc[i][j][1] + b1 + Cadd[r0 * 128 + col + 1]));
                } else {
                    float2 o;
                    o.x = gelu_exact(acc[i][j][0] + b0);
                    o.y = gelu_exact(acc[i][j][1] + b1);
                    *(float2*)&C[r0 * 128 + col] = o;
                }
            }
            if (r1 < M) {
                if (MODE == 1) {
                    *(float2*)&C[r1 * 128 + col] = make_float2(acc[i][j][2], acc[i][j][3]);
                } else if (MODE == 3) {
                    *(__half2*)&Ch[r1 * 128 + col] = __floats2half2_rn(
                        gelu_exact(acc[i][j][2] + b0), gelu_exact(acc[i][j][3] + b1));
                } else if (MODE == 4) {
                    *(__half2*)&Ch[r1 * 128 + col] = __floats2half2_rn(
                        gelu_exact(acc[i][j][2] + b0 + Cadd[r1 * 128 + col]),
                        gelu_exact(acc[i][j][3] + b1 + Cadd[r1 * 128 + col + 1]));
                } else {
                    float2 o;
                    o.x = gelu_exact(acc[i][j][2] + b0);
                    o.y = gelu_exact(acc[i][j][3] + b1);
                    *(float2*)&C[r1 * 128 + col] = o;
                }
            }
        }
    }
}

// ---------------- launch -----------------------------------------------------
extern "C" void kernel_launch(void* const* d_in, const int* in_sizes, int n_in,
                              void* d_out, int out_size) {
    static StreamPack sp;   // first call = correctness run (not captured)

    const float* node_repr = (const float*)d_in[0];
    const int*   edges     = (const int*)d_in[1];
    const float* ew        = (const float*)d_in[2];
    const float *p0g = (const float*)d_in[3],  *p0b = (const float*)d_in[4],
                *p0m = (const float*)d_in[5],  *p0v = (const float*)d_in[6],
                *p0W = (const float*)d_in[7],  *p0bi = (const float*)d_in[8];
    const float *p1g = (const float*)d_in[9],  *p1b = (const float*)d_in[10],
                *p1m = (const float*)d_in[11], *p1v = (const float*)d_in[12],
                *p1W = (const float*)d_in[13], *p1bi = (const float*)d_in[14];
    const float *u0g = (const float*)d_in[15], *u0b = (const float*)d_in[16],
                *u0m = (const float*)d_in[17], *u0v = (const float*)d_in[18],
                *u0W = (const float*)d_in[19], *u0bi = (const float*)d_in[20];
    const float *u1g = (const float*)d_in[21], *u1b = (const float*)d_in[22],
                *u1m = (const float*)d_in[23], *u1v = (const float*)d_in[24],
                *u1W = (const float*)d_in[25], *u1bi = (const float*)d_in[26];
    float* out = (float*)d_out;

    __half *Wp0h, *Wp1h, *Wu0h, *Wu1h, *Ph, *Th, *AGGh;
    float *bp0, *bp1, *bu0, *bu1, *PART;
    int* csr;
    cudaGetSymbolAddress((void**)&Wp0h, g_Wp0h);
    cudaGetSymbolAddress((void**)&Wp1h, g_Wp1h);
    cudaGetSymbolAddress((void**)&Wu0h, g_Wu0h);
    cudaGetSymbolAddress((void**)&Wu1h, g_Wu1h);
    cudaGetSymbolAddress((void**)&bp0, g_bp0);
    cudaGetSymbolAddress((void**)&bp1, g_bp1);
    cudaGetSymbolAddress((void**)&bu0, g_bu0);
    cudaGetSymbolAddress((void**)&bu1, g_bu1);
    cudaGetSymbolAddress((void**)&Th,   g_Th);
    cudaGetSymbolAddress((void**)&Ph,   g_Ph);
    cudaGetSymbolAddress((void**)&AGGh, g_AGGh);
    cudaGetSymbolAddress((void**)&PART, g_PART);
    cudaGetSymbolAddress((void**)&csr,  g_csr);

    cudaStream_t s0 = 0, s1 = sp.s1, s2 = sp.s2;
    const int gm = (NN + BM - 1) / BM;

    // fork point
    cudaEventRecord(sp.ev_root, s0);
    cudaStreamWaitEvent(s1, sp.ev_root, 0);

    // --- s1: CSR chain ---
    cudaMemsetAsync(csr, 0, (2 * NN + 1) * sizeof(int), s1);
    count_kernel<<<(EE + 255) / 256, 256, 0, s1>>>(edges);
    scan_fused_kernel<<<SCAN_NB, SCAN_B, 0, s1>>>();
    fill_kernel<<<(EE + 255) / 256, 256, 0, s1>>>(edges, ew);
    cudaEventRecord(sp.ev_csr, s1);

    // --- s0: fold (fp16 transposed weights) ---
    FoldArgs fa0 = {p0g, p0b, p0m, p0v, p0W, p0bi, Wp0h, bp0, DD, DD};
    FoldArgs fa1 = {p1g, p1b, p1m, p1v, p1W, p1bi, Wp1h, bp1, HH, HH};
    FoldArgs fa2 = {u0g, u0b, u0m, u0v, u0W, u0bi, Wu0h, bu0, KU, KU};
    FoldArgs fa3 = {u1g, u1b, u1m, u1v, u1W, u1bi, Wu1h, bu1, HH, HH};
    fold4_kernel<<<dim3(128, 4), 256, 0, s0>>>(fa0, fa1, fa2, fa3);
    cudaEventRecord(sp.ev_fold, s0);

    // --- s2: upd0 partial = node_repr @ Wu0[:, 0:128] -> PART (fp32) ---
    cudaStreamWaitEvent(s2, sp.ev_fold, 0);
    gemm_f16_k128<1, false><<<gm, 256, 0, s2>>>(node_repr, Wu0h, KU, nullptr, nullptr, PART, NN);
    cudaEventRecord(sp.ev_u0a, s2);

    // --- s0: prep FFN (fp16 intermediates) ---
    gemm_f16_k128<3, false><<<gm, 256, 0, s0>>>(node_repr, Wp0h, DD, bp0, nullptr, Th, NN);
    gemm_f16_k128<3, true ><<<gm, 256, 0, s0>>>(Th,        Wp1h, HH, bp1, nullptr, Ph, NN);

    // join CSR, aggregate (fp16 in/out)
    cudaStreamWaitEvent(s0, sp.ev_csr, 0);
    aggregate_kernel<<<(NN * 32 + 255) / 256, 256, 0, s0>>>();

    // join upd0 partial; upd0b: gelu(AGG @ Wu0[:, 128:256] + PART + bias) -> Th
    cudaStreamWaitEvent(s0, sp.ev_u0a, 0);
    gemm_f16_k128<4, true ><<<gm, 256, 0, s0>>>(AGGh, Wu0h + 128, KU, bu0, PART, Th, NN);
    gemm_f16_k128<0, true ><<<gm, 256, 0, s0>>>(Th, Wu1h, HH, bu1, nullptr, out, NN);
}

// round 14
// speedup vs baseline: 1.3622x; 1.2042x over previous
#include <cuda_runtime.h>
#include <cuda_fp16.h>
#include <math.h>
#include <stdint.h>

#define NN 50000
#define EE 800000
#define DD 128
#define HH 128
#define KU (DD + HH)
#define BN_EPS 1e-3f

#define SCAN_B 256
#define SCAN_NB ((NN + SCAN_B - 1) / SCAN_B)   // 196

// ---------------- scratch (device globals; no allocation allowed) ----------
__device__ __half g_Ph[NN * HH];     // prep output per node (fp16)
__device__ __half g_AGGh[NN * HH];   // aggregated messages (fp16)
// weights: fp16, n-major  Wh[n][k]
__device__ __half g_Wp0h[HH * DD];
__device__ __half g_Wp1h[HH * HH];
__device__ __half g_Wu0h[HH * KU];   // row stride KU=256
__device__ __half g_Wu1h[HH * HH];
__device__ float  g_bp0[HH], g_bp1[HH], g_bu0[HH], g_bu1[HH];
// CSR combined: [cnt NN][cur NN][base 1][start NN]
__device__ int    g_csr[3 * NN + 1];
__device__ int    g_nbr[EE];
__device__ float  g_wgt[EE];

#define CSR_CNT   (g_csr)
#define CSR_CUR   (g_csr + NN)
#define CSR_BASE  (g_csr + 2 * NN)
#define CSR_START (g_csr + 2 * NN + 1)

// ---------------- streams/events (lazy init on first, non-captured call) ----
struct StreamPack {
    cudaStream_t s1;
    cudaEvent_t ev_root, ev_csr;
    StreamPack() {
        cudaStreamCreateWithFlags(&s1, cudaStreamNonBlocking);
        cudaEventCreateWithFlags(&ev_root, cudaEventDisableTiming);
        cudaEventCreateWithFlags(&ev_csr,  cudaEventDisableTiming);
    }
};

// ---------------- BN fold (4 matrices, one launch) --------------------------
struct FoldArgs {
    const float *g, *b, *m, *v, *W, *bi;
    __half *Wo;
    float *bo;
    int K, ldw;
};

__global__ void fold4_kernel(FoldArgs a0, FoldArgs a1, FoldArgs a2, FoldArgs a3) {
    FoldArgs a;
    switch (blockIdx.y) {
        case 0: a = a0; break;
        case 1: a = a1; break;
        case 2: a = a2; break;
        default: a = a3; break;
    }
    int j = blockIdx.x;        // output column (n)
    int k = threadIdx.x;       // input row (k)
    __shared__ float red[256];
    float contrib = 0.0f;
    if (k < a.K) {
        float s = a.g[k] * rsqrtf(a.v[k] + BN_EPS);
        float t = a.b[k] - a.m[k] * s;
        float w = a.W[k * HH + j];
        a.Wo[j * a.ldw + k] = __float2half(s * w);   // transposed, fp16
        contrib = t * w;
    }
    red[k] = contrib;
    __syncthreads();
    for (int st = 128; st > 0; st >>= 1) {
        if (k < st) red[k] += red[k + st];
        __syncthreads();
    }
    if (k == 0) a.bo[j] = a.bi[j] + red[0];
}

// ---------------- CSR build --------------------------------------------------
__global__ void count_kernel(const int* __restrict__ edges) {
    int e = blockIdx.x * blockDim.x + threadIdx.x;
    if (e < EE) atomicAdd(&CSR_CNT[edges[e]], 1);
}

__global__ void scan_fused_kernel() {
    __shared__ int sh[SCAN_B];
    __shared__ int base_sh;
    int t = threadIdx.x;
    int i = blockIdx.x * SCAN_B + t;
    int v = (i < NN) ? CSR_CNT[i] : 0;
    sh[t] = v;
    __syncthreads();
    for (int ofs = 1; ofs < SCAN_B; ofs <<= 1) {
        int u = (t >= ofs) ? sh[t - ofs] : 0;
        __syncthreads();
        sh[t] += u;
        __syncthreads();
    }
    if (t == SCAN_B - 1) base_sh = atomicAdd(CSR_BASE, sh[t]);
    __syncthreads();
    if (i < NN) CSR_START[i] = base_sh + sh[t] - v;
}

__global__ void fill_kernel(const int* __restrict__ edges, const float* __restrict__ ew) {
    int e = blockIdx.x * blockDim.x + threadIdx.x;
    if (e < EE) {
        int dst = edges[e];
        int nbr = edges[EE + e];
        int pos = CSR_START[dst] + atomicAdd(&CSR_CUR[dst], 1);
        g_nbr[pos] = nbr;
        g_wgt[pos] = ew[e];
    }
}

// ---------------- aggregation: one warp per node, fp16 in / fp16 out --------
__global__ void aggregate_kernel() {
    int node = (blockIdx.x * blockDim.x + threadIdx.x) >> 5;
    int lane = threadIdx.x & 31;
    if (node >= NN) return;
    int s = CSR_START[node];
    int cnt = CSR_CNT[node];
    int e = s + cnt;
    float4 acc = make_float4(0.f, 0.f, 0.f, 0.f);
    int i = s;
    for (; i + 4 <= e; i += 4) {
        int   nb0 = __ldg(&g_nbr[i]),     nb1 = __ldg(&g_nbr[i + 1]);
        int   nb2 = __ldg(&g_nbr[i + 2]), nb3 = __ldg(&g_nbr[i + 3]);
        float w0 = __ldg(&g_wgt[i]),      w1 = __ldg(&g_wgt[i + 1]);
        float w2 = __ldg(&g_wgt[i + 2]),  w3 = __ldg(&g_wgt[i + 3]);
        const __half2* p0 = (const __half2*)&g_Ph[nb0 * HH + lane * 4];
        const __half2* p1 = (const __half2*)&g_Ph[nb1 * HH + lane * 4];
        const __half2* p2 = (const __half2*)&g_Ph[nb2 * HH + lane * 4];
        const __half2* p3 = (const __half2*)&g_Ph[nb3 * HH + lane * 4];
        float2 a0 = __half22float2(p0[0]), b0 = __half22float2(p0[1]);
        float2 a1 = __half22float2(p1[0]), b1 = __half22float2(p1[1]);
        float2 a2 = __half22float2(p2[0]), b2 = __half22float2(p2[1]);
        float2 a3 = __half22float2(p3[0]), b3 = __half22float2(p3[1]);
        acc.x += w0 * a0.x + w1 * a1.x + w2 * a2.x + w3 * a3.x;
        acc.y += w0 * a0.y + w1 * a1.y + w2 * a2.y + w3 * a3.y;
        acc.z += w0 * b0.x + w1 * b1.x + w2 * b2.x + w3 * b3.x;
        acc.w += w0 * b0.y + w1 * b1.y + w2 * b2.y + w3 * b3.y;
    }
    for (; i < e; i++) {
        int nb  = __ldg(&g_nbr[i]);
        float w = __ldg(&g_wgt[i]);
        const __half2* p = (const __half2*)&g_Ph[nb * HH + lane * 4];
        float2 a = __half22float2(p[0]), b = __half22float2(p[1]);
        acc.x += w * a.x; acc.y += w * a.y; acc.z += w * b.x; acc.w += w * b.y;
    }
    float inv = (cnt > 0) ? 1.0f / (float)cnt : 0.0f;
    __half2 h0 = __floats2half2_rn(acc.x * inv, acc.y * inv);
    __half2 h1 = __floats2half2_rn(acc.z * inv, acc.w * inv);
    uint2 o;
    o.x = *(uint32_t*)&h0;
    o.y = *(uint32_t*)&h1;
    *(uint2*)&g_AGGh[node * HH + lane * 4] = o;
}

// ---------------- fused 2-layer FFN kernel ----------------------------------
// stage1: acc = A @ W0^T  (UPD: A = [node_repr | AGGh], K=256; else node_repr, K=128)
//         mid = fp16(gelu(acc + b0))   (128x128 tile in smem)
// stage2: out = gelu(mid @ W1^T + b1)  (UPD: fp32 out; else fp16 out)
__device__ __forceinline__ float gelu_exact(float x) {
    return 0.5f * x * (1.0f + erff(x * 0.70710678118654752f));
}

__device__ __forceinline__ void mma_f16(float* d, const uint32_t* a, const uint32_t* b) {
    asm volatile(
        "mma.sync.aligned.m16n8k16.row.col.f32.f16.f16.f32 "
        "{%0,%1,%2,%3}, {%4,%5,%6,%7}, {%8,%9}, {%0,%1,%2,%3};\n"
        : "+f"(d[0]), "+f"(d[1]), "+f"(d[2]), "+f"(d[3])
        : "r"(a[0]), "r"(a[1]), "r"(a[2]), "r"(a[3]), "r"(b[0]), "r"(b[1]));
}

#define BM 128
#define BK 16
#define HS 24       // pipeline smem row stride (halves)
#define MS 136      // mid smem row stride (halves)
#define PIPE_HALves (2 * BM * HS)
#define SM_PIPE_A 0
#define SM_PIPE_B (2 * BM * HS)
#define SM_MID    (4 * BM * HS)
#define FFN_SMEM ((4 * BM * HS + BM * MS) * (int)sizeof(__half))   // 59392 B

template <bool UPD>
__global__ __launch_bounds__(256, 2) void ffn2_kernel(
    const float* __restrict__ A0,     // node_repr [M][128] fp32
    const __half* __restrict__ A1,    // AGGh [M][128] fp16 (UPD only)
    const __half* __restrict__ W0, int ldb0,
    const float* __restrict__ b0,
    const __half* __restrict__ W1,    // ld = 128
    const float* __restrict__ b1,
    void* __restrict__ Cv, int M)
{
    extern __shared__ __half sm[];
    __half* pA  = sm + SM_PIPE_A;   // [2][128][HS]
    __half* pB  = sm + SM_PIPE_B;   // [2][128][HS]
    __half* mid = sm + SM_MID;      // [128][MS]

    const int tid  = threadIdx.x;
    const int lane = tid & 31;
    const int wid  = tid >> 5;
    const int wm = (wid & 3) * 32;
    const int wn = (wid >> 2) * 64;
    const int bm = blockIdx.x * BM;

    const int lr  = tid >> 1;
    const int seg = (tid & 1) * 8;
    const int grow = bm + lr;
    const bool rok = (grow < M);

    const int gi = lane >> 2;
    const int ti = lane & 3;

    const int K1 = UPD ? 256 : 128;

    float acc[2][8][4];
#pragma unroll
    for (int i = 0; i < 2; i++)
#pragma unroll
        for (int j = 0; j < 8; j++)
#pragma unroll
            for (int c = 0; c < 4; c++) acc[i][j][c] = 0.0f;

    uint4 avr, bvr;
    auto load_tile1 = [&](int kc) {
        if (UPD && kc >= 128) {
            avr = make_uint4(0, 0, 0, 0);
            if (rok) avr = *(const uint4*)&A1[grow * 128 + (kc - 128) + seg];
        } else {
            float4 x = make_float4(0.f,0.f,0.f,0.f), y = x;
            if (rok) {
                const float* ap = &A0[grow * 128 + kc + seg];
                x = *(const float4*)(ap);
                y = *(const float4*)(ap + 4);
            }
            __half2 h0 = __floats2half2_rn(x.x, x.y);
            __half2 h1 = __floats2half2_rn(x.z, x.w);
            __half2 h2 = __floats2half2_rn(y.x, y.y);
            __half2 h3 = __floats2half2_rn(y.z, y.w);
            avr.x = *(uint32_t*)&h0; avr.y = *(uint32_t*)&h1;
            avr.z = *(uint32_t*)&h2; avr.w = *(uint32_t*)&h3;
        }
        bvr = *(const uint4*)&W0[lr * ldb0 + kc + seg];
    };

    // ---- stage 1: pipelined GEMM over K1 ----
    load_tile1(0);
    *(uint4*)&pA[(0 * BM + lr) * HS + seg] = avr;
    *(uint4*)&pB[(0 * BM + lr) * HS + seg] = bvr;
    __syncthreads();

    const int NIT = K1 / BK;
    for (int kb = 0; kb < NIT; kb++) {
        const int buf = kb & 1;
        if (kb + 1 < NIT) load_tile1((kb + 1) * BK);

        uint32_t af[2][4];
#pragma unroll
        for (int i = 0; i < 2; i++) {
            const int r = wm + 16 * i + gi;
            af[i][0] = *(const uint32_t*)&pA[(buf * BM + r) * HS + 2 * ti];
            af[i][1] = *(const uint32_t*)&pA[(buf * BM + r + 8) * HS + 2 * ti];
            af[i][2] = *(const uint32_t*)&pA[(buf * BM + r) * HS + 2 * ti + 8];
            af[i][3] = *(const uint32_t*)&pA[(buf * BM + r + 8) * HS + 2 * ti + 8];
        }
        uint32_t bf[8][2];
#pragma unroll
        for (int j = 0; j < 8; j++) {
            const int n = wn + 8 * j + gi;
            bf[j][0] = *(const uint32_t*)&pB[(buf * BM + n) * HS + 2 * ti];
            bf[j][1] = *(const uint32_t*)&pB[(buf * BM + n) * HS + 2 * ti + 8];
        }
#pragma unroll
        for (int i = 0; i < 2; i++)
#pragma unroll
            for (int j = 0; j < 8; j++)
                mma_f16(acc[i][j], af[i], bf[j]);

        if (kb + 1 < NIT) {
            *(uint4*)&pA[((buf ^ 1) * BM + lr) * HS + seg] = avr;
            *(uint4*)&pB[((buf ^ 1) * BM + lr) * HS + seg] = bvr;
            __syncthreads();
        }
    }

    // ---- epilogue 1: gelu + bias -> mid (fp16) ----
#pragma unroll
    for (int j = 0; j < 8; j++) {
        const int col = wn + 8 * j + ti * 2;
        const float c0 = b0[col], c1 = b0[col + 1];
#pragma unroll
        for (int i = 0; i < 2; i++) {
            const int r0 = wm + 16 * i + gi;
            const int r1 = r0 + 8;
            *(__half2*)&mid[r0 * MS + col] = __floats2half2_rn(
                gelu_exact(acc[i][j][0] + c0), gelu_exact(acc[i][j][1] + c1));
            *(__half2*)&mid[r1 * MS + col] = __floats2half2_rn(
                gelu_exact(acc[i][j][2] + c0), gelu_exact(acc[i][j][3] + c1));
            acc[i][j][0] = 0.f; acc[i][j][1] = 0.f;
            acc[i][j][2] = 0.f; acc[i][j][3] = 0.f;
        }
    }
    __syncthreads();   // mid complete; stage1 pipe reads done

    // ---- stage 2: A from mid (smem-resident), B = W1 streamed ----
    bvr = *(const uint4*)&W1[lr * 128 + seg];
    *(uint4*)&pB[(0 * BM + lr) * HS + seg] = bvr;
    __syncthreads();

#pragma unroll
    for (int kb = 0; kb < 8; kb++) {
        const int buf = kb & 1;
        const int k0 = kb * BK;
        if (kb + 1 < 8) bvr = *(const uint4*)&W1[lr * 128 + (kb + 1) * BK + seg];

        uint32_t af[2][4];
#pragma unroll
        for (int i = 0; i < 2; i++) {
            const int r = wm + 16 * i + gi;
            af[i][0] = *(const uint32_t*)&mid[r * MS + k0 + 2 * ti];
            af[i][1] = *(const uint32_t*)&mid[(r + 8) * MS + k0 + 2 * ti];
            af[i][2] = *(const uint32_t*)&mid[r * MS + k0 + 2 * ti + 8];
            af[i][3] = *(const uint32_t*)&mid[(r + 8) * MS + k0 + 2 * ti + 8];
        }
        uint32_t bf[8][2];
#pragma unroll
        for (int j = 0; j < 8; j++) {
            const int n = wn + 8 * j + gi;
            bf[j][0] = *(const uint32_t*)&pB[(buf * BM + n) * HS + 2 * ti];
            bf[j][1] = *(const uint32_t*)&pB[(buf * BM + n) * HS + 2 * ti + 8];
        }
#pragma unroll
        for (int i = 0; i < 2; i++)
#pragma unroll
            for (int j = 0; j < 8; j++)
                mma_f16(acc[i][j], af[i], bf[j]);

        if (kb + 1 < 8) {
            *(uint4*)&pB[((buf ^ 1) * BM + lr) * HS + seg] = bvr;
            __syncthreads();
        }
    }

    // ---- epilogue 2 ----
    float* C  = (float*)Cv;
    __half* Ch = (__half*)Cv;
#pragma unroll
    for (int j = 0; j < 8; j++) {
        const int col = wn + 8 * j + ti * 2;
        const float c0 = b1[col], c1 = b1[col + 1];
#pragma unroll
        for (int i = 0; i < 2; i++) {
            const int r0 = bm + wm + 16 * i + gi;
            const int r1 = r0 + 8;
            if (r0 < M) {
                if (UPD) {
                    float2 o;
                    o.x = gelu_exact(acc[i][j][0] + c0);
                    o.y = gelu_exact(acc[i][j][1] + c1);
                    *(float2*)&C[r0 * 128 + col] = o;
                } else {
                    *(__half2*)&Ch[r0 * 128 + col] = __floats2half2_rn(
                        gelu_exact(acc[i][j][0] + c0), gelu_exact(acc[i][j][1] + c1));
                }
            }
            if (r1 < M) {
                if (UPD) {
                    float2 o;
                    o.x = gelu_exact(acc[i][j][2] + c0);
                    o.y = gelu_exact(acc[i][j][3] + c1);
                    *(float2*)&C[r1 * 128 + col] = o;
                } else {
                    *(__half2*)&Ch[r1 * 128 + col] = __floats2half2_rn(
                        gelu_exact(acc[i][j][2] + c0), gelu_exact(acc[i][j][3] + c1));
                }
            }
        }
    }
}

// ---------------- launch -----------------------------------------------------
extern "C" void kernel_launch(void* const* d_in, const int* in_sizes, int n_in,
                              void* d_out, int out_size) {
    static StreamPack sp;   // first call = correctness run (not captured)

    const float* node_repr = (const float*)d_in[0];
    const int*   edges     = (const int*)d_in[1];
    const float* ew        = (const float*)d_in[2];
    const float *p0g = (const float*)d_in[3],  *p0b = (const float*)d_in[4],
                *p0m = (const float*)d_in[5],  *p0v = (const float*)d_in[6],
                *p0W = (const float*)d_in[7],  *p0bi = (const float*)d_in[8];
    const float *p1g = (const float*)d_in[9],  *p1b = (const float*)d_in[10],
                *p1m = (const float*)d_in[11], *p1v = (const float*)d_in[12],
                *p1W = (const float*)d_in[13], *p1bi = (const float*)d_in[14];
    const float *u0g = (const float*)d_in[15], *u0b = (const float*)d_in[16],
                *u0m = (const float*)d_in[17], *u0v = (const float*)d_in[18],
                *u0W = (const float*)d_in[19], *u0bi = (const float*)d_in[20];
    const float *u1g = (const float*)d_in[21], *u1b = (const float*)d_in[22],
                *u1m = (const float*)d_in[23], *u1v = (const float*)d_in[24],
                *u1W = (const float*)d_in[25], *u1bi = (const float*)d_in[26];
    float* out = (float*)d_out;

    __half *Wp0h, *Wp1h, *Wu0h, *Wu1h, *Ph, *AGGh;
    float *bp0, *bp1, *bu0, *bu1;
    int* csr;
    cudaGetSymbolAddress((void**)&Wp0h, g_Wp0h);
    cudaGetSymbolAddress((void**)&Wp1h, g_Wp1h);
    cudaGetSymbolAddress((void**)&Wu0h, g_Wu0h);
    cudaGetSymbolAddress((void**)&Wu1h, g_Wu1h);
    cudaGetSymbolAddress((void**)&bp0, g_bp0);
    cudaGetSymbolAddress((void**)&bp1, g_bp1);
    cudaGetSymbolAddress((void**)&bu0, g_bu0);
    cudaGetSymbolAddress((void**)&bu1, g_bu1);
    cudaGetSymbolAddress((void**)&Ph,   g_Ph);
    cudaGetSymbolAddress((void**)&AGGh, g_AGGh);
    cudaGetSymbolAddress((void**)&csr,  g_csr);

    // opt-in dynamic smem > 48KB (host-side attr set; no allocation)
    cudaFuncSetAttribute(ffn2_kernel<false>, cudaFuncAttributeMaxDynamicSharedMemorySize, FFN_SMEM);
    cudaFuncSetAttribute(ffn2_kernel<true >, cudaFuncAttributeMaxDynamicSharedMemorySize, FFN_SMEM);

    cudaStream_t s0 = 0, s1 = sp.s1;
    const int gm = (NN + BM - 1) / BM;

    // fork point
    cudaEventRecord(sp.ev_root, s0);
    cudaStreamWaitEvent(s1, sp.ev_root, 0);

    // --- s1: CSR chain ---
    cudaMemsetAsync(csr, 0, (2 * NN + 1) * sizeof(int), s1);
    count_kernel<<<(EE + 255) / 256, 256, 0, s1>>>(edges);
    scan_fused_kernel<<<SCAN_NB, SCAN_B, 0, s1>>>();
    fill_kernel<<<(EE + 255) / 256, 256, 0, s1>>>(edges, ew);
    cudaEventRecord(sp.ev_csr, s1);

    // --- s0: fold (fp16 transposed weights) ---
    FoldArgs fa0 = {p0g, p0b, p0m, p0v, p0W, p0bi, Wp0h, bp0, DD, DD};
    FoldArgs fa1 = {p1g, p1b, p1m, p1v, p1W, p1bi, Wp1h, bp1, HH, HH};
    FoldArgs fa2 = {u0g, u0b, u0m, u0v, u0W, u0bi, Wu0h, bu0, KU, KU};
    FoldArgs fa3 = {u1g, u1b, u1m, u1v, u1W, u1bi, Wu1h, bu1, HH, HH};
    fold4_kernel<<<dim3(128, 4), 256, 0, s0>>>(fa0, fa1, fa2, fa3);

    // --- s0: fused prep FFN (both layers) -> Ph ---
    ffn2_kernel<false><<<gm, 256, FFN_SMEM, s0>>>(
        node_repr, nullptr, Wp0h, DD, bp0, Wp1h, bp1, Ph, NN);

    // join CSR, aggregate (fp16 in/out)
    cudaStreamWaitEvent(s0, sp.ev_csr, 0);
    aggregate_kernel<<<(NN * 32 + 255) / 256, 256, 0, s0>>>();

    // --- s0: fused update FFN (split-K concat + both layers) -> out ---
    ffn2_kernel<true><<<gm, 256, FFN_SMEM, s0>>>(
        node_repr, AGGh, Wu0h, KU, bu0, Wu1h, bu1, out, NN);
}